// round 14
// baseline (speedup 1.0000x reference)
#include <cuda_runtime.h>
#include <math_constants.h>
#include <cstdint>

#define Bb   2
#define Nq   2048
#define Mk   4096
#define Dd   256
#define Hh   8
#define DK   32
#define KNNk 16

// ---------------- scratch ----------------
__device__ float g_Q[(size_t)Bb * Nq * Dd];
__device__ float g_K[(size_t)Bb * Mk * Dd];
__device__ float g_V[(size_t)Bb * Mk * Dd];
__device__ float g_X[(size_t)Bb * Nq * Dd];
__device__ float g_T0[(size_t)Bb * Nq * Dd];
__device__ float g_T1[(size_t)Bb * Nq * Dd];
__device__ float g_Hb[(size_t)Bb * Nq * Dd];

// ---------------- tf32 helpers ----------------
__device__ __forceinline__ uint32_t f2tf32(float f) {
    uint32_t r;
    asm("cvt.rna.tf32.f32 %0, %1;" : "=r"(r) : "f"(f));
    return r;
}
__device__ __forceinline__ void mma_tf32(float c[4], uint32_t a0, uint32_t a1,
                                         uint32_t a2, uint32_t a3,
                                         uint32_t b0, uint32_t b1) {
    asm volatile(
        "mma.sync.aligned.m16n8k8.row.col.f32.tf32.tf32.f32 "
        "{%0,%1,%2,%3}, {%4,%5,%6,%7}, {%8,%9}, {%0,%1,%2,%3};"
        : "+f"(c[0]), "+f"(c[1]), "+f"(c[2]), "+f"(c[3])
        : "r"(a0), "r"(a1), "r"(a2), "r"(a3), "r"(b0), "r"(b1));
}

// ============== split-K=2 tf32 GEMM (R10/R12 proven) ==============
__global__ __launch_bounds__(256) void gemm_tf32_splitk_kernel(
    const float* __restrict__ A, const float* __restrict__ W,
    const float* __restrict__ bias,
    float* __restrict__ C0, float* __restrict__ C1)
{
    __shared__ uint32_t As[128][36];
    __shared__ uint32_t Ws[32][68];

    const int tid    = threadIdx.x;
    const int lane   = tid & 31;
    const int wid    = tid >> 5;
    const int warp_m = wid & 3;
    const int warp_n = wid >> 2;
    const int row0   = blockIdx.y * 128;
    const int col0   = blockIdx.x * 64;
    const int z      = blockIdx.z;
    const int kbase  = z * 128;
    float* C = z ? C1 : C0;

    float acc[2][4][4];
#pragma unroll
    for (int mt = 0; mt < 2; mt++)
#pragma unroll
        for (int nt = 0; nt < 4; nt++)
#pragma unroll
            for (int i = 0; i < 4; i++) acc[mt][nt][i] = 0.f;

    float4 ra[4], rw[2];
#pragma unroll
    for (int u = 0; u < 4; u++) {
        int id = u * 256 + tid, r = id >> 3, kq = id & 7;
        ra[u] = *(const float4*)&A[(size_t)(row0 + r) * 256 + kbase + kq * 4];
    }
#pragma unroll
    for (int u = 0; u < 2; u++) {
        int id = u * 256 + tid, k = id >> 4, nq = id & 15;
        rw[u] = *(const float4*)&W[(size_t)(kbase + k) * 256 + col0 + nq * 4];
    }

    for (int it = 0; it < 4; it++) {
#pragma unroll
        for (int u = 0; u < 4; u++) {
            int id = u * 256 + tid, r = id >> 3, kq = id & 7;
            As[r][kq * 4 + 0] = f2tf32(ra[u].x);
            As[r][kq * 4 + 1] = f2tf32(ra[u].y);
            As[r][kq * 4 + 2] = f2tf32(ra[u].z);
            As[r][kq * 4 + 3] = f2tf32(ra[u].w);
        }
#pragma unroll
        for (int u = 0; u < 2; u++) {
            int id = u * 256 + tid, k = id >> 4, nq = id & 15;
            Ws[k][nq * 4 + 0] = f2tf32(rw[u].x);
            Ws[k][nq * 4 + 1] = f2tf32(rw[u].y);
            Ws[k][nq * 4 + 2] = f2tf32(rw[u].z);
            Ws[k][nq * 4 + 3] = f2tf32(rw[u].w);
        }
        __syncthreads();

        if (it < 3) {
            const int k0n = kbase + (it + 1) * 32;
#pragma unroll
            for (int u = 0; u < 4; u++) {
                int id = u * 256 + tid, r = id >> 3, kq = id & 7;
                ra[u] = *(const float4*)&A[(size_t)(row0 + r) * 256 + k0n + kq * 4];
            }
#pragma unroll
            for (int u = 0; u < 2; u++) {
                int id = u * 256 + tid, k = id >> 4, nq = id & 15;
                rw[u] = *(const float4*)&W[(size_t)(k0n + k) * 256 + col0 + nq * 4];
            }
        }

#pragma unroll
        for (int kk = 0; kk < 4; kk++) {
            const int ko = kk * 8;
            uint32_t af[2][4];
#pragma unroll
            for (int mt = 0; mt < 2; mt++) {
                const int mb = warp_m * 32 + mt * 16 + (lane >> 2);
                const int kc = ko + (lane & 3);
                af[mt][0] = As[mb][kc];
                af[mt][1] = As[mb + 8][kc];
                af[mt][2] = As[mb][kc + 4];
                af[mt][3] = As[mb + 8][kc + 4];
            }
#pragma unroll
            for (int nt = 0; nt < 4; nt++) {
                const int nb = warp_n * 32 + nt * 8 + (lane >> 2);
                const int kr = ko + (lane & 3);
                uint32_t b0 = Ws[kr][nb];
                uint32_t b1 = Ws[kr + 4][nb];
#pragma unroll
                for (int mt = 0; mt < 2; mt++)
                    mma_tf32(acc[mt][nt], af[mt][0], af[mt][1], af[mt][2], af[mt][3], b0, b1);
            }
        }
        __syncthreads();
    }

#pragma unroll
    for (int nt = 0; nt < 4; nt++) {
        const int col = col0 + warp_n * 32 + nt * 8 + (lane & 3) * 2;
        const float b0 = z ? 0.f : bias[col];
        const float b1 = z ? 0.f : bias[col + 1];
#pragma unroll
        for (int mt = 0; mt < 2; mt++) {
            const int row = row0 + warp_m * 32 + mt * 16 + (lane >> 2);
            *(float2*)&C[(size_t)row * 256 + col] =
                make_float2(acc[mt][nt][0] + b0, acc[mt][nt][1] + b1);
            *(float2*)&C[(size_t)(row + 8) * 256 + col] =
                make_float2(acc[mt][nt][2] + b0, acc[mt][nt][3] + b1);
        }
    }
}

// ============ fused front GEMM: blocks 0..255 = KV dual, 256..383 = Q single (R9) ========
__global__ __launch_bounds__(256) void gemm_tf32_front_kernel(
    const float* __restrict__ tgt_fea, const float* __restrict__ src_fea,
    const float* __restrict__ Wk, const float* __restrict__ bk,
    const float* __restrict__ Wv, const float* __restrict__ bv,
    const float* __restrict__ Wq, const float* __restrict__ bq,
    float* __restrict__ K, float* __restrict__ V, float* __restrict__ Q)
{
    __shared__ uint32_t As[128][36];
    __shared__ uint32_t WsK[32][68];
    __shared__ uint32_t WsV[32][68];

    const int bid  = blockIdx.x;
    const bool isQ = bid >= 256;
    const int  lb  = isQ ? bid - 256 : bid;

    const float* A  = isQ ? src_fea : tgt_fea;
    const float* WK = isQ ? Wq : Wk;
    const float* bK = isQ ? bq : bk;
    float*       CK = isQ ? Q  : K;

    const int tid    = threadIdx.x;
    const int lane   = tid & 31;
    const int wid    = tid >> 5;
    const int warp_m = wid & 3;
    const int warp_n = wid >> 2;
    const int row0   = (lb >> 2) * 128;
    const int col0   = (lb & 3) * 64;

    float accK[2][4][4], accV[2][4][4];
#pragma unroll
    for (int mt = 0; mt < 2; mt++)
#pragma unroll
        for (int nt = 0; nt < 4; nt++)
#pragma unroll
            for (int i = 0; i < 4; i++) { accK[mt][nt][i] = 0.f; accV[mt][nt][i] = 0.f; }

    float4 ra[4], rk[2], rv[2];
#pragma unroll
    for (int u = 0; u < 4; u++) {
        int id = u * 256 + tid, r = id >> 3, kq = id & 7;
        ra[u] = *(const float4*)&A[(size_t)(row0 + r) * 256 + kq * 4];
    }
#pragma unroll
    for (int u = 0; u < 2; u++) {
        int id = u * 256 + tid, k = id >> 4, nq = id & 15;
        rk[u] = *(const float4*)&WK[(size_t)k * 256 + col0 + nq * 4];
    }
    if (!isQ) {
#pragma unroll
        for (int u = 0; u < 2; u++) {
            int id = u * 256 + tid, k = id >> 4, nq = id & 15;
            rv[u] = *(const float4*)&Wv[(size_t)k * 256 + col0 + nq * 4];
        }
    }

    for (int it = 0; it < 8; it++) {
#pragma unroll
        for (int u = 0; u < 4; u++) {
            int id = u * 256 + tid, r = id >> 3, kq = id & 7;
            As[r][kq * 4 + 0] = f2tf32(ra[u].x);
            As[r][kq * 4 + 1] = f2tf32(ra[u].y);
            As[r][kq * 4 + 2] = f2tf32(ra[u].z);
            As[r][kq * 4 + 3] = f2tf32(ra[u].w);
        }
#pragma unroll
        for (int u = 0; u < 2; u++) {
            int id = u * 256 + tid, k = id >> 4, nq = id & 15;
            WsK[k][nq * 4 + 0] = f2tf32(rk[u].x);
            WsK[k][nq * 4 + 1] = f2tf32(rk[u].y);
            WsK[k][nq * 4 + 2] = f2tf32(rk[u].z);
            WsK[k][nq * 4 + 3] = f2tf32(rk[u].w);
        }
        if (!isQ) {
#pragma unroll
            for (int u = 0; u < 2; u++) {
                int id = u * 256 + tid, k = id >> 4, nq = id & 15;
                WsV[k][nq * 4 + 0] = f2tf32(rv[u].x);
                WsV[k][nq * 4 + 1] = f2tf32(rv[u].y);
                WsV[k][nq * 4 + 2] = f2tf32(rv[u].z);
                WsV[k][nq * 4 + 3] = f2tf32(rv[u].w);
            }
        }
        __syncthreads();

        if (it < 7) {
            const int k0n = (it + 1) * 32;
#pragma unroll
            for (int u = 0; u < 4; u++) {
                int id = u * 256 + tid, r = id >> 3, kq = id & 7;
                ra[u] = *(const float4*)&A[(size_t)(row0 + r) * 256 + k0n + kq * 4];
            }
#pragma unroll
            for (int u = 0; u < 2; u++) {
                int id = u * 256 + tid, k = id >> 4, nq = id & 15;
                rk[u] = *(const float4*)&WK[(size_t)(k0n + k) * 256 + col0 + nq * 4];
            }
            if (!isQ) {
#pragma unroll
                for (int u = 0; u < 2; u++) {
                    int id = u * 256 + tid, k = id >> 4, nq = id & 15;
                    rv[u] = *(const float4*)&Wv[(size_t)(k0n + k) * 256 + col0 + nq * 4];
                }
            }
        }

#pragma unroll
        for (int kk = 0; kk < 4; kk++) {
            const int ko = kk * 8;
            uint32_t af[2][4];
#pragma unroll
            for (int mt = 0; mt < 2; mt++) {
                const int mb = warp_m * 32 + mt * 16 + (lane >> 2);
                const int kc = ko + (lane & 3);
                af[mt][0] = As[mb][kc];
                af[mt][1] = As[mb + 8][kc];
                af[mt][2] = As[mb][kc + 4];
                af[mt][3] = As[mb + 8][kc + 4];
            }
#pragma unroll
            for (int nt = 0; nt < 4; nt++) {
                const int nb = warp_n * 32 + nt * 8 + (lane >> 2);
                const int kr = ko + (lane & 3);
                uint32_t bk0 = WsK[kr][nb], bk1 = WsK[kr + 4][nb];
#pragma unroll
                for (int mt = 0; mt < 2; mt++)
                    mma_tf32(accK[mt][nt], af[mt][0], af[mt][1], af[mt][2], af[mt][3], bk0, bk1);
            }
            if (!isQ) {
#pragma unroll
                for (int nt = 0; nt < 4; nt++) {
                    const int nb = warp_n * 32 + nt * 8 + (lane >> 2);
                    const int kr = ko + (lane & 3);
                    uint32_t bv0 = WsV[kr][nb], bv1 = WsV[kr + 4][nb];
#pragma unroll
                    for (int mt = 0; mt < 2; mt++)
                        mma_tf32(accV[mt][nt], af[mt][0], af[mt][1], af[mt][2], af[mt][3], bv0, bv1);
                }
            }
        }
        __syncthreads();
    }

#pragma unroll
    for (int nt = 0; nt < 4; nt++) {
        const int col = col0 + warp_n * 32 + nt * 8 + (lane & 3) * 2;
        const float bk0 = bK[col], bk1 = bK[col + 1];
#pragma unroll
        for (int mt = 0; mt < 2; mt++) {
            const int row = row0 + warp_m * 32 + mt * 16 + (lane >> 2);
            *(float2*)&CK[(size_t)row * 256 + col] =
                make_float2(accK[mt][nt][0] + bk0, accK[mt][nt][1] + bk1);
            *(float2*)&CK[(size_t)(row + 8) * 256 + col] =
                make_float2(accK[mt][nt][2] + bk0, accK[mt][nt][3] + bk1);
        }
    }
    if (!isQ) {
#pragma unroll
        for (int nt = 0; nt < 4; nt++) {
            const int col = col0 + warp_n * 32 + nt * 8 + (lane & 3) * 2;
            const float bv0 = bv[col], bv1 = bv[col + 1];
#pragma unroll
            for (int mt = 0; mt < 2; mt++) {
                const int row = row0 + warp_m * 32 + mt * 16 + (lane >> 2);
                *(float2*)&V[(size_t)row * 256 + col] =
                    make_float2(accV[mt][nt][0] + bv0, accV[mt][nt][1] + bv1);
                *(float2*)&V[(size_t)(row + 8) * 256 + col] =
                    make_float2(accV[mt][nt][2] + bv0, accV[mt][nt][3] + bv1);
            }
        }
    }
}

// ============ fused kNN + sparse attention: one block per query ============
// Phase 1: register-resident top-16 selection (256 threads, 16 dists each).
// Phase 2: R8-proven attention (K gather to smem, softmax, vectorized V gather).
#define KSTRIDE 261
#define PSTRIDE 264

__global__ __launch_bounds__(256) void knn_attn_kernel(
    const float* __restrict__ src, const float* __restrict__ tgt,
    const float* __restrict__ src_fea, float* __restrict__ avg_attn)
{
    __shared__ float sK[KNNk][KSTRIDE];   // K tile; reused as partial buffer
    __shared__ float lmin[256];
    __shared__ int   lidx[256];
    __shared__ int   s_win;
    __shared__ int   sidx[KNNk];
    __shared__ float sq[Dd];
    __shared__ float sattn[Hh][KNNk];

    const int qid = blockIdx.x;
    const int b   = qid / Nq;
    const int tid = threadIdx.x;

    // avg_attn row zero-fill first (independent stores overlap the compute below)
    float* rowp = avg_attn + (size_t)qid * Mk;
    float4 zz = make_float4(0.f, 0.f, 0.f, 0.f);
#pragma unroll
    for (int i = 0; i < 4; i++) ((float4*)rowp)[tid + i * 256] = zz;

    // Q feature row (independent)
    sq[tid] = g_Q[(size_t)qid * Dd + tid];

    // ---- kNN phase: 16 register-resident distances per thread ----
    const float qx = src[(size_t)qid * 3 + 0];
    const float qy = src[(size_t)qid * 3 + 1];
    const float qz = src[(size_t)qid * 3 + 2];
    const float qq = qx * qx + qy * qy + qz * qz;
    const float* tb = tgt + (size_t)b * Mk * 3;

    float d[16];
    float bm = CUDART_INF_F;
    int   bi = Mk;
#pragma unroll
    for (int i = 0; i < 16; i++) {
        const int m = i * 256 + tid;
        float x = tb[(size_t)m * 3 + 0];
        float y = tb[(size_t)m * 3 + 1];
        float z = tb[(size_t)m * 3 + 2];
        float sqv = fmaxf(qq + (x * x + y * y + z * z) - 2.f * (qx * x + qy * y + qz * z), 0.f);
        d[i] = sqv;
        if (sqv < bm) { bm = sqv; bi = m; }
    }
    lmin[tid] = bm; lidx[tid] = bi;
    __syncthreads();

    uint32_t mask = 0;
    for (int it = 0; it < KNNk; it++) {
        if (tid < 32) {
            float v = lmin[tid]; int ix = lidx[tid];
#pragma unroll
            for (int j = 32; j < 256; j += 32) {
                float v2 = lmin[tid + j]; int i2 = lidx[tid + j];
                if (v2 < v || (v2 == v && i2 < ix)) { v = v2; ix = i2; }
            }
#pragma unroll
            for (int o = 16; o > 0; o >>= 1) {
                float v2 = __shfl_xor_sync(0xFFFFFFFFu, v, o);
                int   i2 = __shfl_xor_sync(0xFFFFFFFFu, ix, o);
                if (v2 < v || (v2 == v && i2 < ix)) { v = v2; ix = i2; }
            }
            if (tid == 0) {
                s_win = ix;
                sidx[it] = ix;
            }
        }
        __syncthreads();
        if (it < KNNk - 1) {
            const int win = s_win;
            if (tid == (win & 255)) {
                mask |= 1u << (win >> 8);
                float nb = CUDART_INF_F; int ni = Mk;
#pragma unroll
                for (int i = 0; i < 16; i++) {
                    if (!(mask & (1u << i)) && d[i] < nb) { nb = d[i]; ni = i * 256 + tid; }
                }
                lmin[tid] = nb; lidx[tid] = ni;
            }
            __syncthreads();
        }
    }
    __syncthreads();   // sidx complete & visible

    // ---- attention phase (R8 proven) ----
    {
        const int c4 = tid & 63;
        const int rg = tid >> 6;
#pragma unroll
        for (int it = 0; it < 4; it++) {
            const int r = rg + it * 4;
            float4 kv = *(const float4*)&g_K[((size_t)b * Mk + sidx[r]) * Dd + c4 * 4];
            sK[r][c4 * 4 + 0] = kv.x; sK[r][c4 * 4 + 1] = kv.y;
            sK[r][c4 * 4 + 2] = kv.z; sK[r][c4 * 4 + 3] = kv.w;
        }
    }
    __syncthreads();

    if (tid < Hh * KNNk) {
        const int h = tid >> 4;
        const int j = tid & 15;
        float s = 0.f;
#pragma unroll
        for (int dd = 0; dd < DK; dd++) s += sq[h * DK + dd] * sK[j][h * DK + dd];
        s *= 0.17677669529663687f;

        float m = s;
#pragma unroll
        for (int o = 8; o > 0; o >>= 1) m = fmaxf(m, __shfl_xor_sync(0xFFFFFFFFu, m, o));
        float e = __expf(s - m);
        float sum = e;
#pragma unroll
        for (int o = 8; o > 0; o >>= 1) sum += __shfl_xor_sync(0xFFFFFFFFu, sum, o);
        sattn[h][j] = e / sum;
    }
    __syncthreads();

    {
        float* spart = &sK[0][0];
        const int c4 = tid & 63;
        const int jg = tid >> 6;
        const int h  = c4 >> 3;
        const float w0 = sattn[h][jg * 4 + 0];
        const float w1 = sattn[h][jg * 4 + 1];
        const float w2 = sattn[h][jg * 4 + 2];
        const float w3 = sattn[h][jg * 4 + 3];
        const float* vb = g_V + (size_t)b * Mk * Dd + c4 * 4;
        float4 v0 = *(const float4*)&vb[(size_t)sidx[jg * 4 + 0] * Dd];
        float4 v1 = *(const float4*)&vb[(size_t)sidx[jg * 4 + 1] * Dd];
        float4 v2 = *(const float4*)&vb[(size_t)sidx[jg * 4 + 2] * Dd];
        float4 v3 = *(const float4*)&vb[(size_t)sidx[jg * 4 + 3] * Dd];
        float4 a;
        a.x = w0 * v0.x + w1 * v1.x + w2 * v2.x + w3 * v3.x;
        a.y = w0 * v0.y + w1 * v1.y + w2 * v2.y + w3 * v3.y;
        a.z = w0 * v0.z + w1 * v1.z + w2 * v2.z + w3 * v3.z;
        a.w = w0 * v0.w + w1 * v1.w + w2 * v2.w + w3 * v3.w;
        *(float4*)&spart[jg * PSTRIDE + c4 * 4] = a;
        __syncthreads();
        const int dd = tid;
        float o = spart[dd] + spart[PSTRIDE + dd] + spart[2 * PSTRIDE + dd] + spart[3 * PSTRIDE + dd];
        g_X[(size_t)qid * Dd + dd] = o + src_fea[(size_t)qid * Dd + dd];
    }

    // scatter avg_attn (row zeroed at kernel start; all barriers since order the writes)
    if (tid < KNNk) {
        float a = 0.f;
#pragma unroll
        for (int h = 0; h < Hh; h++) a += sattn[h][tid];
        rowp[sidx[tid]] = a * 0.125f;
    }
}

// ============ LayerNorm + ReLU: warp-per-row (R12 proven) ============
__global__ __launch_bounds__(256) void ln_relu_kernel(
    const float* __restrict__ T0, const float* __restrict__ T1,
    const float* __restrict__ gam, const float* __restrict__ bet,
    float* __restrict__ Hb)
{
    const int lane = threadIdx.x & 31;
    const int wrp  = threadIdx.x >> 5;
    const int row  = blockIdx.x * 8 + wrp;
    const size_t base = (size_t)row * Dd;

    const int c0 = lane * 4;
    const int c1 = 128 + lane * 4;

    float4 a0 = *(const float4*)&T0[base + c0];
    float4 b0 = *(const float4*)&T1[base + c0];
    float4 a1 = *(const float4*)&T0[base + c1];
    float4 b1 = *(const float4*)&T1[base + c1];

    float x0 = a0.x + b0.x, x1 = a0.y + b0.y, x2 = a0.z + b0.z, x3 = a0.w + b0.w;
    float x4 = a1.x + b1.x, x5 = a1.y + b1.y, x6 = a1.z + b1.z, x7 = a1.w + b1.w;

    float s = ((x0 + x1) + (x2 + x3)) + ((x4 + x5) + (x6 + x7));
#pragma unroll
    for (int o = 16; o > 0; o >>= 1) s += __shfl_xor_sync(0xFFFFFFFFu, s, o);
    const float mu = s * (1.f / 256.f);

    float d0 = x0 - mu, d1 = x1 - mu, d2 = x2 - mu, d3 = x3 - mu;
    float d4 = x4 - mu, d5 = x5 - mu, d6 = x6 - mu, d7 = x7 - mu;
    float s2 = ((d0 * d0 + d1 * d1) + (d2 * d2 + d3 * d3))
             + ((d4 * d4 + d5 * d5) + (d6 * d6 + d7 * d7));
#pragma unroll
    for (int o = 16; o > 0; o >>= 1) s2 += __shfl_xor_sync(0xFFFFFFFFu, s2, o);
    const float rstd = rsqrtf(s2 * (1.f / 256.f) + 1e-5f);

    float4 g0 = *(const float4*)&gam[c0];
    float4 g1 = *(const float4*)&gam[c1];
    float4 e0 = *(const float4*)&bet[c0];
    float4 e1 = *(const float4*)&bet[c1];

    float4 o0, o1;
    o0.x = fmaxf(d0 * rstd * g0.x + e0.x, 0.f);
    o0.y = fmaxf(d1 * rstd * g0.y + e0.y, 0.f);
    o0.z = fmaxf(d2 * rstd * g0.z + e0.z, 0.f);
    o0.w = fmaxf(d3 * rstd * g0.w + e0.w, 0.f);
    o1.x = fmaxf(d4 * rstd * g1.x + e1.x, 0.f);
    o1.y = fmaxf(d5 * rstd * g1.y + e1.y, 0.f);
    o1.z = fmaxf(d6 * rstd * g1.z + e1.z, 0.f);
    o1.w = fmaxf(d7 * rstd * g1.w + e1.w, 0.f);

    *(float4*)&Hb[base + c0] = o0;
    *(float4*)&Hb[base + c1] = o1;
}

// ======================= add partials: upd = P0 + P1 =======================
__global__ __launch_bounds__(256) void add_kernel(
    const float* __restrict__ P0, const float* __restrict__ P1,
    float* __restrict__ out)
{
    const size_t i = ((size_t)blockIdx.x * 256 + threadIdx.x) * 4;
    float4 a = *(const float4*)&P0[i];
    float4 b = *(const float4*)&P1[i];
    float4 r;
    r.x = a.x + b.x; r.y = a.y + b.y; r.z = a.z + b.z; r.w = a.w + b.w;
    *(float4*)&out[i] = r;
}

// ======================= launch =======================
extern "C" void kernel_launch(void* const* d_in, const int* in_sizes, int n_in,
                              void* d_out, int out_size)
{
    const float* src     = (const float*)d_in[0];
    const float* tgt     = (const float*)d_in[1];
    const float* src_fea = (const float*)d_in[2];
    const float* tgt_fea = (const float*)d_in[3];
    const float* Wq  = (const float*)d_in[4];  const float* bq  = (const float*)d_in[5];
    const float* Wk  = (const float*)d_in[6];  const float* bk  = (const float*)d_in[7];
    const float* Wv  = (const float*)d_in[8];  const float* bv  = (const float*)d_in[9];
    const float* Wo1 = (const float*)d_in[10]; const float* bo1 = (const float*)d_in[11];
    const float* lng = (const float*)d_in[12]; const float* lnb = (const float*)d_in[13];
    const float* Wo2 = (const float*)d_in[14]; const float* bo2 = (const float*)d_in[15];

    float* outp = (float*)d_out;
    float* upd  = outp;
    float* avg  = outp + (size_t)Bb * Nq * Dd;

    float *pQ, *pK, *pV, *pX, *pT0, *pT1, *pHb;
    cudaGetSymbolAddress((void**)&pQ,  g_Q);
    cudaGetSymbolAddress((void**)&pK,  g_K);
    cudaGetSymbolAddress((void**)&pV,  g_V);
    cudaGetSymbolAddress((void**)&pX,  g_X);
    cudaGetSymbolAddress((void**)&pT0, g_T0);
    cudaGetSymbolAddress((void**)&pT1, g_T1);
    cudaGetSymbolAddress((void**)&pHb, g_Hb);

    // fused front: KV dual (256 blocks) + Q single (128 blocks)
    gemm_tf32_front_kernel<<<384, 256>>>(tgt_fea, src_fea, Wk, bk, Wv, bv, Wq, bq,
                                         pK, pV, pQ);

    // fused kNN + attention (one block per query)
    knn_attn_kernel<<<Bb * Nq, 256>>>(src, tgt, src_fea, avg);

    // Wo1: split-K=2, partials summed inside ln_relu
    gemm_tf32_splitk_kernel<<<dim3(4, (Bb * Nq) / 128, 2), 256>>>(pX, Wo1, bo1, pT0, pT1);
    ln_relu_kernel<<<(Bb * Nq) / 8, 256>>>(pT0, pT1, lng, lnb, pHb);

    // Wo2: split-K=2, partials added into the output
    gemm_tf32_splitk_kernel<<<dim3(4, (Bb * Nq) / 128, 2), 256>>>(pHb, Wo2, bo2, pT0, pT1);
    add_kernel<<<(Bb * Nq * Dd) / 1024, 256>>>(pT0, pT1, upd);
}

// round 15
// speedup vs baseline: 1.0704x; 1.0704x over previous
#include <cuda_runtime.h>
#include <math_constants.h>
#include <cstdint>

#define Bb   2
#define Nq   2048
#define Mk   4096
#define Dd   256
#define Hh   8
#define DK   32
#define KNNk 16

// ---------------- scratch ----------------
__device__ float g_Q[(size_t)Bb * Nq * Dd];
__device__ float g_K[(size_t)Bb * Mk * Dd];
__device__ float g_V[(size_t)Bb * Mk * Dd];
__device__ float g_X[(size_t)Bb * Nq * Dd];
__device__ float g_T0[(size_t)Bb * Nq * Dd];
__device__ float g_T1[(size_t)Bb * Nq * Dd];
__device__ float g_Hb[(size_t)Bb * Nq * Dd];
__device__ int   g_idx[(size_t)Bb * Nq * KNNk];

// ---------------- tf32 helpers ----------------
__device__ __forceinline__ uint32_t f2tf32(float f) {
    uint32_t r;
    asm("cvt.rna.tf32.f32 %0, %1;" : "=r"(r) : "f"(f));
    return r;
}
__device__ __forceinline__ void mma_tf32(float c[4], uint32_t a0, uint32_t a1,
                                         uint32_t a2, uint32_t a3,
                                         uint32_t b0, uint32_t b1) {
    asm volatile(
        "mma.sync.aligned.m16n8k8.row.col.f32.tf32.tf32.f32 "
        "{%0,%1,%2,%3}, {%4,%5,%6,%7}, {%8,%9}, {%0,%1,%2,%3};"
        : "+f"(c[0]), "+f"(c[1]), "+f"(c[2]), "+f"(c[3])
        : "r"(a0), "r"(a1), "r"(a2), "r"(a3), "r"(b0), "r"(b1));
}

// ============== split-K=2 tf32 GEMM (R10/R12 proven) ==============
__global__ __launch_bounds__(256) void gemm_tf32_splitk_kernel(
    const float* __restrict__ A, const float* __restrict__ W,
    const float* __restrict__ bias,
    float* __restrict__ C0, float* __restrict__ C1)
{
    __shared__ uint32_t As[128][36];
    __shared__ uint32_t Ws[32][68];

    const int tid    = threadIdx.x;
    const int lane   = tid & 31;
    const int wid    = tid >> 5;
    const int warp_m = wid & 3;
    const int warp_n = wid >> 2;
    const int row0   = blockIdx.y * 128;
    const int col0   = blockIdx.x * 64;
    const int z      = blockIdx.z;
    const int kbase  = z * 128;
    float* C = z ? C1 : C0;

    float acc[2][4][4];
#pragma unroll
    for (int mt = 0; mt < 2; mt++)
#pragma unroll
        for (int nt = 0; nt < 4; nt++)
#pragma unroll
            for (int i = 0; i < 4; i++) acc[mt][nt][i] = 0.f;

    float4 ra[4], rw[2];
#pragma unroll
    for (int u = 0; u < 4; u++) {
        int id = u * 256 + tid, r = id >> 3, kq = id & 7;
        ra[u] = *(const float4*)&A[(size_t)(row0 + r) * 256 + kbase + kq * 4];
    }
#pragma unroll
    for (int u = 0; u < 2; u++) {
        int id = u * 256 + tid, k = id >> 4, nq = id & 15;
        rw[u] = *(const float4*)&W[(size_t)(kbase + k) * 256 + col0 + nq * 4];
    }

    for (int it = 0; it < 4; it++) {
#pragma unroll
        for (int u = 0; u < 4; u++) {
            int id = u * 256 + tid, r = id >> 3, kq = id & 7;
            As[r][kq * 4 + 0] = f2tf32(ra[u].x);
            As[r][kq * 4 + 1] = f2tf32(ra[u].y);
            As[r][kq * 4 + 2] = f2tf32(ra[u].z);
            As[r][kq * 4 + 3] = f2tf32(ra[u].w);
        }
#pragma unroll
        for (int u = 0; u < 2; u++) {
            int id = u * 256 + tid, k = id >> 4, nq = id & 15;
            Ws[k][nq * 4 + 0] = f2tf32(rw[u].x);
            Ws[k][nq * 4 + 1] = f2tf32(rw[u].y);
            Ws[k][nq * 4 + 2] = f2tf32(rw[u].z);
            Ws[k][nq * 4 + 3] = f2tf32(rw[u].w);
        }
        __syncthreads();

        if (it < 3) {
            const int k0n = kbase + (it + 1) * 32;
#pragma unroll
            for (int u = 0; u < 4; u++) {
                int id = u * 256 + tid, r = id >> 3, kq = id & 7;
                ra[u] = *(const float4*)&A[(size_t)(row0 + r) * 256 + k0n + kq * 4];
            }
#pragma unroll
            for (int u = 0; u < 2; u++) {
                int id = u * 256 + tid, k = id >> 4, nq = id & 15;
                rw[u] = *(const float4*)&W[(size_t)(k0n + k) * 256 + col0 + nq * 4];
            }
        }

#pragma unroll
        for (int kk = 0; kk < 4; kk++) {
            const int ko = kk * 8;
            uint32_t af[2][4];
#pragma unroll
            for (int mt = 0; mt < 2; mt++) {
                const int mb = warp_m * 32 + mt * 16 + (lane >> 2);
                const int kc = ko + (lane & 3);
                af[mt][0] = As[mb][kc];
                af[mt][1] = As[mb + 8][kc];
                af[mt][2] = As[mb][kc + 4];
                af[mt][3] = As[mb + 8][kc + 4];
            }
#pragma unroll
            for (int nt = 0; nt < 4; nt++) {
                const int nb = warp_n * 32 + nt * 8 + (lane >> 2);
                const int kr = ko + (lane & 3);
                uint32_t b0 = Ws[kr][nb];
                uint32_t b1 = Ws[kr + 4][nb];
#pragma unroll
                for (int mt = 0; mt < 2; mt++)
                    mma_tf32(acc[mt][nt], af[mt][0], af[mt][1], af[mt][2], af[mt][3], b0, b1);
            }
        }
        __syncthreads();
    }

#pragma unroll
    for (int nt = 0; nt < 4; nt++) {
        const int col = col0 + warp_n * 32 + nt * 8 + (lane & 3) * 2;
        const float b0 = z ? 0.f : bias[col];
        const float b1 = z ? 0.f : bias[col + 1];
#pragma unroll
        for (int mt = 0; mt < 2; mt++) {
            const int row = row0 + warp_m * 32 + mt * 16 + (lane >> 2);
            *(float2*)&C[(size_t)row * 256 + col] =
                make_float2(acc[mt][nt][0] + b0, acc[mt][nt][1] + b1);
            *(float2*)&C[(size_t)(row + 8) * 256 + col] =
                make_float2(acc[mt][nt][2] + b0, acc[mt][nt][3] + b1);
        }
    }
}

// ============ fused front GEMM: blocks 0..255 = KV dual, 256..383 = Q single (R9) ========
__global__ __launch_bounds__(256) void gemm_tf32_front_kernel(
    const float* __restrict__ tgt_fea, const float* __restrict__ src_fea,
    const float* __restrict__ Wk, const float* __restrict__ bk,
    const float* __restrict__ Wv, const float* __restrict__ bv,
    const float* __restrict__ Wq, const float* __restrict__ bq,
    float* __restrict__ K, float* __restrict__ V, float* __restrict__ Q)
{
    __shared__ uint32_t As[128][36];
    __shared__ uint32_t WsK[32][68];
    __shared__ uint32_t WsV[32][68];

    const int bid  = blockIdx.x;
    const bool isQ = bid >= 256;
    const int  lb  = isQ ? bid - 256 : bid;

    const float* A  = isQ ? src_fea : tgt_fea;
    const float* WK = isQ ? Wq : Wk;
    const float* bK = isQ ? bq : bk;
    float*       CK = isQ ? Q  : K;

    const int tid    = threadIdx.x;
    const int lane   = tid & 31;
    const int wid    = tid >> 5;
    const int warp_m = wid & 3;
    const int warp_n = wid >> 2;
    const int row0   = (lb >> 2) * 128;
    const int col0   = (lb & 3) * 64;

    float accK[2][4][4], accV[2][4][4];
#pragma unroll
    for (int mt = 0; mt < 2; mt++)
#pragma unroll
        for (int nt = 0; nt < 4; nt++)
#pragma unroll
            for (int i = 0; i < 4; i++) { accK[mt][nt][i] = 0.f; accV[mt][nt][i] = 0.f; }

    float4 ra[4], rk[2], rv[2];
#pragma unroll
    for (int u = 0; u < 4; u++) {
        int id = u * 256 + tid, r = id >> 3, kq = id & 7;
        ra[u] = *(const float4*)&A[(size_t)(row0 + r) * 256 + kq * 4];
    }
#pragma unroll
    for (int u = 0; u < 2; u++) {
        int id = u * 256 + tid, k = id >> 4, nq = id & 15;
        rk[u] = *(const float4*)&WK[(size_t)k * 256 + col0 + nq * 4];
    }
    if (!isQ) {
#pragma unroll
        for (int u = 0; u < 2; u++) {
            int id = u * 256 + tid, k = id >> 4, nq = id & 15;
            rv[u] = *(const float4*)&Wv[(size_t)k * 256 + col0 + nq * 4];
        }
    }

    for (int it = 0; it < 8; it++) {
#pragma unroll
        for (int u = 0; u < 4; u++) {
            int id = u * 256 + tid, r = id >> 3, kq = id & 7;
            As[r][kq * 4 + 0] = f2tf32(ra[u].x);
            As[r][kq * 4 + 1] = f2tf32(ra[u].y);
            As[r][kq * 4 + 2] = f2tf32(ra[u].z);
            As[r][kq * 4 + 3] = f2tf32(ra[u].w);
        }
#pragma unroll
        for (int u = 0; u < 2; u++) {
            int id = u * 256 + tid, k = id >> 4, nq = id & 15;
            WsK[k][nq * 4 + 0] = f2tf32(rk[u].x);
            WsK[k][nq * 4 + 1] = f2tf32(rk[u].y);
            WsK[k][nq * 4 + 2] = f2tf32(rk[u].z);
            WsK[k][nq * 4 + 3] = f2tf32(rk[u].w);
        }
        if (!isQ) {
#pragma unroll
            for (int u = 0; u < 2; u++) {
                int id = u * 256 + tid, k = id >> 4, nq = id & 15;
                WsV[k][nq * 4 + 0] = f2tf32(rv[u].x);
                WsV[k][nq * 4 + 1] = f2tf32(rv[u].y);
                WsV[k][nq * 4 + 2] = f2tf32(rv[u].z);
                WsV[k][nq * 4 + 3] = f2tf32(rv[u].w);
            }
        }
        __syncthreads();

        if (it < 7) {
            const int k0n = (it + 1) * 32;
#pragma unroll
            for (int u = 0; u < 4; u++) {
                int id = u * 256 + tid, r = id >> 3, kq = id & 7;
                ra[u] = *(const float4*)&A[(size_t)(row0 + r) * 256 + k0n + kq * 4];
            }
#pragma unroll
            for (int u = 0; u < 2; u++) {
                int id = u * 256 + tid, k = id >> 4, nq = id & 15;
                rk[u] = *(const float4*)&WK[(size_t)(k0n + k) * 256 + col0 + nq * 4];
            }
            if (!isQ) {
#pragma unroll
                for (int u = 0; u < 2; u++) {
                    int id = u * 256 + tid, k = id >> 4, nq = id & 15;
                    rv[u] = *(const float4*)&Wv[(size_t)(k0n + k) * 256 + col0 + nq * 4];
                }
            }
        }

#pragma unroll
        for (int kk = 0; kk < 4; kk++) {
            const int ko = kk * 8;
            uint32_t af[2][4];
#pragma unroll
            for (int mt = 0; mt < 2; mt++) {
                const int mb = warp_m * 32 + mt * 16 + (lane >> 2);
                const int kc = ko + (lane & 3);
                af[mt][0] = As[mb][kc];
                af[mt][1] = As[mb + 8][kc];
                af[mt][2] = As[mb][kc + 4];
                af[mt][3] = As[mb + 8][kc + 4];
            }
#pragma unroll
            for (int nt = 0; nt < 4; nt++) {
                const int nb = warp_n * 32 + nt * 8 + (lane >> 2);
                const int kr = ko + (lane & 3);
                uint32_t bk0 = WsK[kr][nb], bk1 = WsK[kr + 4][nb];
#pragma unroll
                for (int mt = 0; mt < 2; mt++)
                    mma_tf32(accK[mt][nt], af[mt][0], af[mt][1], af[mt][2], af[mt][3], bk0, bk1);
            }
            if (!isQ) {
#pragma unroll
                for (int nt = 0; nt < 4; nt++) {
                    const int nb = warp_n * 32 + nt * 8 + (lane >> 2);
                    const int kr = ko + (lane & 3);
                    uint32_t bv0 = WsV[kr][nb], bv1 = WsV[kr + 4][nb];
#pragma unroll
                    for (int mt = 0; mt < 2; mt++)
                        mma_tf32(accV[mt][nt], af[mt][0], af[mt][1], af[mt][2], af[mt][3], bv0, bv1);
                }
            }
        }
        __syncthreads();
    }

#pragma unroll
    for (int nt = 0; nt < 4; nt++) {
        const int col = col0 + warp_n * 32 + nt * 8 + (lane & 3) * 2;
        const float bk0 = bK[col], bk1 = bK[col + 1];
#pragma unroll
        for (int mt = 0; mt < 2; mt++) {
            const int row = row0 + warp_m * 32 + mt * 16 + (lane >> 2);
            *(float2*)&CK[(size_t)row * 256 + col] =
                make_float2(accK[mt][nt][0] + bk0, accK[mt][nt][1] + bk1);
            *(float2*)&CK[(size_t)(row + 8) * 256 + col] =
                make_float2(accK[mt][nt][2] + bk0, accK[mt][nt][3] + bk1);
        }
    }
    if (!isQ) {
#pragma unroll
        for (int nt = 0; nt < 4; nt++) {
            const int col = col0 + warp_n * 32 + nt * 8 + (lane & 3) * 2;
            const float bv0 = bv[col], bv1 = bv[col + 1];
#pragma unroll
            for (int mt = 0; mt < 2; mt++) {
                const int row = row0 + warp_m * 32 + mt * 16 + (lane >> 2);
                *(float2*)&V[(size_t)row * 256 + col] =
                    make_float2(accV[mt][nt][0] + bv0, accV[mt][nt][1] + bv1);
                *(float2*)&V[(size_t)(row + 8) * 256 + col] =
                    make_float2(accV[mt][nt][2] + bv0, accV[mt][nt][3] + bv1);
            }
        }
    }
}

// ======================= kNN: lazy-rescan top-16 (R3 verbatim) =======================
__global__ __launch_bounds__(128) void knn_kernel(
    const float* __restrict__ src, const float* __restrict__ tgt,
    int* __restrict__ knn_idx)
{
    __shared__ float dist[Mk];
    __shared__ float lmin[128];
    __shared__ int   lidx[128];
    __shared__ int   s_win;

    const int qid = blockIdx.x;
    const int b   = qid / Nq;
    const int tid = threadIdx.x;

    const float qx = src[(size_t)qid * 3 + 0];
    const float qy = src[(size_t)qid * 3 + 1];
    const float qz = src[(size_t)qid * 3 + 2];
    const float qq = qx * qx + qy * qy + qz * qz;
    const float* tb = tgt + (size_t)b * Mk * 3;

    float bm = CUDART_INF_F;
    int   bi = Mk;
    for (int m = tid; m < Mk; m += 128) {
        float x = tb[(size_t)m * 3 + 0];
        float y = tb[(size_t)m * 3 + 1];
        float z = tb[(size_t)m * 3 + 2];
        float sq = fmaxf(qq + (x * x + y * y + z * z) - 2.f * (qx * x + qy * y + qz * z), 0.f);
        dist[m] = sq;
        if (sq < bm) { bm = sq; bi = m; }
    }
    lmin[tid] = bm; lidx[tid] = bi;
    __syncthreads();

    for (int it = 0; it < KNNk; it++) {
        if (tid < 32) {
            float v = lmin[tid]; int ix = lidx[tid];
#pragma unroll
            for (int j = 32; j < 128; j += 32) {
                float v2 = lmin[tid + j]; int i2 = lidx[tid + j];
                if (v2 < v || (v2 == v && i2 < ix)) { v = v2; ix = i2; }
            }
#pragma unroll
            for (int o = 16; o > 0; o >>= 1) {
                float v2 = __shfl_xor_sync(0xFFFFFFFFu, v, o);
                int   i2 = __shfl_xor_sync(0xFFFFFFFFu, ix, o);
                if (v2 < v || (v2 == v && i2 < ix)) { v = v2; ix = i2; }
            }
            if (tid == 0) {
                s_win = ix;
                knn_idx[(size_t)qid * KNNk + it] = ix;
                dist[ix] = CUDART_INF_F;
            }
        }
        __syncthreads();
        if (it < KNNk - 1) {
            int owner = s_win & 127;
            if (tid == owner) {
                float nb = CUDART_INF_F; int ni = Mk;
                for (int m = tid; m < Mk; m += 128) {
                    float v = dist[m];
                    if (v < nb) { nb = v; ni = m; }
                }
                lmin[tid] = nb; lidx[tid] = ni;
            }
            __syncthreads();
        }
    }
}

// ======================= sparse attention (R8 + streaming zero-fill) =======================
#define KSTRIDE 261
#define PSTRIDE 264

__global__ __launch_bounds__(256) void attn_kernel(const float* __restrict__ src_fea,
                                                   float* __restrict__ avg_attn)
{
    __shared__ int   sidx[KNNk];
    __shared__ float sq[Dd];
    __shared__ float sattn[Hh][KNNk];
    __shared__ float sK[KNNk][KSTRIDE];

    const int qid = blockIdx.x;
    const int b   = qid / Nq;
    const int tid = threadIdx.x;

    if (tid < KNNk) sidx[tid] = g_idx[(size_t)qid * KNNk + tid];
    sq[tid] = g_Q[(size_t)qid * Dd + tid];
    __syncthreads();

    {
        const int c4 = tid & 63;
        const int rg = tid >> 6;
#pragma unroll
        for (int it = 0; it < 4; it++) {
            const int r = rg + it * 4;
            float4 kv = *(const float4*)&g_K[((size_t)b * Mk + sidx[r]) * Dd + c4 * 4];
            sK[r][c4 * 4 + 0] = kv.x; sK[r][c4 * 4 + 1] = kv.y;
            sK[r][c4 * 4 + 2] = kv.z; sK[r][c4 * 4 + 3] = kv.w;
        }
    }
    __syncthreads();

    if (tid < Hh * KNNk) {
        const int h = tid >> 4;
        const int j = tid & 15;
        float s = 0.f;
#pragma unroll
        for (int d = 0; d < DK; d++) s += sq[h * DK + d] * sK[j][h * DK + d];
        s *= 0.17677669529663687f;

        float m = s;
#pragma unroll
        for (int o = 8; o > 0; o >>= 1) m = fmaxf(m, __shfl_xor_sync(0xFFFFFFFFu, m, o));
        float e = __expf(s - m);
        float sum = e;
#pragma unroll
        for (int o = 8; o > 0; o >>= 1) sum += __shfl_xor_sync(0xFFFFFFFFu, sum, o);
        sattn[h][j] = e / sum;
    }
    __syncthreads();

    {
        float* spart = &sK[0][0];
        const int c4 = tid & 63;
        const int jg = tid >> 6;
        const int h  = c4 >> 3;
        const float w0 = sattn[h][jg * 4 + 0];
        const float w1 = sattn[h][jg * 4 + 1];
        const float w2 = sattn[h][jg * 4 + 2];
        const float w3 = sattn[h][jg * 4 + 3];
        const float* vb = g_V + (size_t)b * Mk * Dd + c4 * 4;
        float4 v0 = *(const float4*)&vb[(size_t)sidx[jg * 4 + 0] * Dd];
        float4 v1 = *(const float4*)&vb[(size_t)sidx[jg * 4 + 1] * Dd];
        float4 v2 = *(const float4*)&vb[(size_t)sidx[jg * 4 + 2] * Dd];
        float4 v3 = *(const float4*)&vb[(size_t)sidx[jg * 4 + 3] * Dd];
        float4 a;
        a.x = w0 * v0.x + w1 * v1.x + w2 * v2.x + w3 * v3.x;
        a.y = w0 * v0.y + w1 * v1.y + w2 * v2.y + w3 * v3.y;
        a.z = w0 * v0.z + w1 * v1.z + w2 * v2.z + w3 * v3.z;
        a.w = w0 * v0.w + w1 * v1.w + w2 * v2.w + w3 * v3.w;
        *(float4*)&spart[jg * PSTRIDE + c4 * 4] = a;
        __syncthreads();
        const int d = tid;
        float o = spart[d] + spart[PSTRIDE + d] + spart[2 * PSTRIDE + d] + spart[3 * PSTRIDE + d];
        g_X[(size_t)qid * Dd + d] = o + src_fea[(size_t)qid * Dd + d];
    }

    // avg_attn zero-fill with cache-streaming stores (don't evict K/V from L2)
    float* rowp = avg_attn + (size_t)qid * Mk;
    float4 z = make_float4(0.f, 0.f, 0.f, 0.f);
#pragma unroll
    for (int i = 0; i < 4; i++) __stcs(&((float4*)rowp)[tid + i * 256], z);
    __syncthreads();
    if (tid < KNNk) {
        float a = 0.f;
#pragma unroll
        for (int h = 0; h < Hh; h++) a += sattn[h][tid];
        rowp[sidx[tid]] = a * 0.125f;
    }
}

// ============ LayerNorm + ReLU: warp-per-row (R12 proven) ============
__global__ __launch_bounds__(256) void ln_relu_kernel(
    const float* __restrict__ T0, const float* __restrict__ T1,
    const float* __restrict__ gam, const float* __restrict__ bet,
    float* __restrict__ Hb)
{
    const int lane = threadIdx.x & 31;
    const int wrp  = threadIdx.x >> 5;
    const int row  = blockIdx.x * 8 + wrp;
    const size_t base = (size_t)row * Dd;

    const int c0 = lane * 4;
    const int c1 = 128 + lane * 4;

    float4 a0 = *(const float4*)&T0[base + c0];
    float4 b0 = *(const float4*)&T1[base + c0];
    float4 a1 = *(const float4*)&T0[base + c1];
    float4 b1 = *(const float4*)&T1[base + c1];

    float x0 = a0.x + b0.x, x1 = a0.y + b0.y, x2 = a0.z + b0.z, x3 = a0.w + b0.w;
    float x4 = a1.x + b1.x, x5 = a1.y + b1.y, x6 = a1.z + b1.z, x7 = a1.w + b1.w;

    float s = ((x0 + x1) + (x2 + x3)) + ((x4 + x5) + (x6 + x7));
#pragma unroll
    for (int o = 16; o > 0; o >>= 1) s += __shfl_xor_sync(0xFFFFFFFFu, s, o);
    const float mu = s * (1.f / 256.f);

    float d0 = x0 - mu, d1 = x1 - mu, d2 = x2 - mu, d3 = x3 - mu;
    float d4 = x4 - mu, d5 = x5 - mu, d6 = x6 - mu, d7 = x7 - mu;
    float s2 = ((d0 * d0 + d1 * d1) + (d2 * d2 + d3 * d3))
             + ((d4 * d4 + d5 * d5) + (d6 * d6 + d7 * d7));
#pragma unroll
    for (int o = 16; o > 0; o >>= 1) s2 += __shfl_xor_sync(0xFFFFFFFFu, s2, o);
    const float rstd = rsqrtf(s2 * (1.f / 256.f) + 1e-5f);

    float4 g0 = *(const float4*)&gam[c0];
    float4 g1 = *(const float4*)&gam[c1];
    float4 e0 = *(const float4*)&bet[c0];
    float4 e1 = *(const float4*)&bet[c1];

    float4 o0, o1;
    o0.x = fmaxf(d0 * rstd * g0.x + e0.x, 0.f);
    o0.y = fmaxf(d1 * rstd * g0.y + e0.y, 0.f);
    o0.z = fmaxf(d2 * rstd * g0.z + e0.z, 0.f);
    o0.w = fmaxf(d3 * rstd * g0.w + e0.w, 0.f);
    o1.x = fmaxf(d4 * rstd * g1.x + e1.x, 0.f);
    o1.y = fmaxf(d5 * rstd * g1.y + e1.y, 0.f);
    o1.z = fmaxf(d6 * rstd * g1.z + e1.z, 0.f);
    o1.w = fmaxf(d7 * rstd * g1.w + e1.w, 0.f);

    *(float4*)&Hb[base + c0] = o0;
    *(float4*)&Hb[base + c1] = o1;
}

// ======================= add partials: upd = P0 + P1 =======================
__global__ __launch_bounds__(256) void add_kernel(
    const float* __restrict__ P0, const float* __restrict__ P1,
    float* __restrict__ out)
{
    const size_t i = ((size_t)blockIdx.x * 256 + threadIdx.x) * 4;
    float4 a = *(const float4*)&P0[i];
    float4 b = *(const float4*)&P1[i];
    float4 r;
    r.x = a.x + b.x; r.y = a.y + b.y; r.z = a.z + b.z; r.w = a.w + b.w;
    *(float4*)&out[i] = r;
}

// ======================= launch =======================
extern "C" void kernel_launch(void* const* d_in, const int* in_sizes, int n_in,
                              void* d_out, int out_size)
{
    const float* src     = (const float*)d_in[0];
    const float* tgt     = (const float*)d_in[1];
    const float* src_fea = (const float*)d_in[2];
    const float* tgt_fea = (const float*)d_in[3];
    const float* Wq  = (const float*)d_in[4];  const float* bq  = (const float*)d_in[5];
    const float* Wk  = (const float*)d_in[6];  const float* bk  = (const float*)d_in[7];
    const float* Wv  = (const float*)d_in[8];  const float* bv  = (const float*)d_in[9];
    const float* Wo1 = (const float*)d_in[10]; const float* bo1 = (const float*)d_in[11];
    const float* lng = (const float*)d_in[12]; const float* lnb = (const float*)d_in[13];
    const float* Wo2 = (const float*)d_in[14]; const float* bo2 = (const float*)d_in[15];

    float* outp = (float*)d_out;
    float* upd  = outp;
    float* avg  = outp + (size_t)Bb * Nq * Dd;

    float *pQ, *pK, *pV, *pX, *pT0, *pT1, *pHb; int* pIdx;
    cudaGetSymbolAddress((void**)&pQ,  g_Q);
    cudaGetSymbolAddress((void**)&pK,  g_K);
    cudaGetSymbolAddress((void**)&pV,  g_V);
    cudaGetSymbolAddress((void**)&pX,  g_X);
    cudaGetSymbolAddress((void**)&pT0, g_T0);
    cudaGetSymbolAddress((void**)&pT1, g_T1);
    cudaGetSymbolAddress((void**)&pHb, g_Hb);
    cudaGetSymbolAddress((void**)&pIdx, g_idx);

    knn_kernel<<<Bb * Nq, 128>>>(src, tgt, pIdx);

    // fused front: KV dual (256 blocks) + Q single (128 blocks)
    gemm_tf32_front_kernel<<<384, 256>>>(tgt_fea, src_fea, Wk, bk, Wv, bv, Wq, bq,
                                         pK, pV, pQ);

    attn_kernel<<<Bb * Nq, 256>>>(src_fea, avg);

    // Wo1: split-K=2, partials summed inside ln_relu
    gemm_tf32_splitk_kernel<<<dim3(4, (Bb * Nq) / 128, 2), 256>>>(pX, Wo1, bo1, pT0, pT1);
    ln_relu_kernel<<<(Bb * Nq) / 8, 256>>>(pT0, pT1, lng, lnb, pHb);

    // Wo2: split-K=2, partials added into the output
    gemm_tf32_splitk_kernel<<<dim3(4, (Bb * Nq) / 128, 2), 256>>>(pHb, Wo2, bo2, pT0, pT1);
    add_kernel<<<(Bb * Nq * Dd) / 1024, 256>>>(pT0, pT1, upd);
}